// round 12
// baseline (speedup 1.0000x reference)
#include <cuda_runtime.h>

// out[n,p,d] = feat[n,p,d] * mean_m(task[n,m,p])
// n=32, m=16, p=1024, d=512

static constexpr int N = 32;
static constexpr int M = 16;
static constexpr int P = 1024;
static constexpr int D = 512;
static constexpr int NP  = N * P;        // 32768 rows
static constexpr int D8  = D / 8;        // 64 float8 (32B units) per row

static constexpr int TPB = 256;
static constexpr int R   = 8;            // rows per CTA == warps per CTA
static constexpr int C8  = R * D8;       // 512 float8 per CTA
static constexpr int U   = 2;            // float8 chunks per thread (64 B)
static constexpr int GRID = NP / R;      // 4096 CTAs

// 256-bit evict_last load (ptxas requires v8.b32 with .L2::evict_last).
// feat is 64 MB, re-read every replay; L2 is 126 MB. evict_last keeps feat
// resident while the out-write stream evicts its own lines.
struct F8 { float4 a, b; };
__device__ __forceinline__ F8 ldg256_evict_last(const void* p) {
    F8 v;
    asm("ld.global.L2::evict_last.v8.b32 {%0,%1,%2,%3,%4,%5,%6,%7}, [%8];"
        : "=f"(v.a.x), "=f"(v.a.y), "=f"(v.a.z), "=f"(v.a.w),
          "=f"(v.b.x), "=f"(v.b.y), "=f"(v.b.z), "=f"(v.b.w)
        : "l"(p));
    return v;
}

__global__ void __launch_bounds__(TPB) fused_kernel(
    const float* __restrict__ task,     // [N, M, P]
    const float* __restrict__ feat,     // [N, P, D]
    float* __restrict__ out)            // [N, P, D]
{
    __shared__ float s_mean[R];

    const int tid   = threadIdx.x;
    const int lane  = tid & 31;
    const int w     = tid >> 5;                  // 0..7, also the local row
    const int base8 = blockIdx.x * C8 + tid;     // float8 index, 32-bit

    // ---- 1) Issue the bulk feat loads first (2 independent 256-bit LDG,
    //         evict_last). They remain in flight across the barrier.
    F8 v[U];
#pragma unroll
    for (int k = 0; k < U; ++k)
        v[k] = ldg256_evict_last(feat + (size_t)(base8 + k * TPB) * 8);

    // ---- 2) Each warp computes ONE row mean (row == warp id).
    {
        const int grow = blockIdx.x * R + w;     // global (n,p) row
        const int n    = grow >> 10;             // P = 1024
        const int p    = grow & (P - 1);
        float x = 0.0f;
        if (lane < M)
            x = task[n * (M * P) + lane * P + p];   // lane = m index
        x += __shfl_xor_sync(0xFFFFFFFFu, x, 8);
        x += __shfl_xor_sync(0xFFFFFFFFu, x, 4);
        x += __shfl_xor_sync(0xFFFFFFFFu, x, 2);
        x += __shfl_xor_sync(0xFFFFFFFFu, x, 1);
        if (lane == 0)
            s_mean[w] = x * (1.0f / (float)M);
    }
    __syncthreads();

    // ---- 3) Multiply + store. Chunk k lives in local row
    //         (k*256 + w*32 + lane) >> 6 == 4k + (w>>1)  (warp-uniform).
    float4* o = reinterpret_cast<float4*>(out);
#pragma unroll
    for (int k = 0; k < U; ++k) {
        const float mn = s_mean[4 * k + (w >> 1)];
        v[k].a.x *= mn; v[k].a.y *= mn; v[k].a.z *= mn; v[k].a.w *= mn;
        v[k].b.x *= mn; v[k].b.y *= mn; v[k].b.z *= mn; v[k].b.w *= mn;
        const int i4 = 2 * (base8 + k * TPB);
        o[i4]     = v[k].a;
        o[i4 + 1] = v[k].b;
    }
}

extern "C" void kernel_launch(void* const* d_in, const int* in_sizes, int n_in,
                              void* d_out, int out_size)
{
    const float* task = (const float*)d_in[0];   // [N, M, P]
    const float* feat = (const float*)d_in[1];   // [N, P, D]
    float* out = (float*)d_out;

    fused_kernel<<<GRID, TPB>>>(task, feat, out);
}

// round 13
// speedup vs baseline: 1.0890x; 1.0890x over previous
#include <cuda_runtime.h>

// out[n,p,d] = feat[n,p,d] * mean_m(task[n,m,p])
// n=32, m=16, p=1024, d=512

static constexpr int N = 32;
static constexpr int M = 16;
static constexpr int P = 1024;
static constexpr int D = 512;
static constexpr int NP  = N * P;        // 32768 rows
static constexpr int D4  = D / 4;        // 128 float4 per row

static constexpr int TPB = 512;
static constexpr int R   = 16;           // rows per CTA == warps per CTA
static constexpr int C4  = R * D4;       // 2048 float4 per CTA
static constexpr int U   = 4;            // float4 per thread (C4 / TPB)
static constexpr int GRID = NP / R;      // 2048 CTAs

__global__ void __launch_bounds__(TPB) fused_kernel(
    const float* __restrict__ task,     // [N, M, P]
    const float* __restrict__ feat,     // [N, P, D]
    float* __restrict__ out)            // [N, P, D]
{
    __shared__ float s_mean[R];

    const int tid   = threadIdx.x;
    const int lane  = tid & 31;
    const int w     = tid >> 5;                  // 0..15, also the local row
    const int base4 = blockIdx.x * C4 + tid;     // fits 32-bit

    const float4* f = reinterpret_cast<const float4*>(feat);
    float4*       o = reinterpret_cast<float4*>(out);

    // ---- 1) Issue the bulk feat loads first (4 independent LDG.128).
    //         They remain in flight across the barrier below.
    float4 v[U];
#pragma unroll
    for (int k = 0; k < U; ++k)
        v[k] = f[base4 + k * TPB];

    // ---- 2) Each warp computes ONE row mean (row == warp id).
    {
        const int grow = blockIdx.x * R + w;     // global (n,p) row
        const int n    = grow >> 10;             // P = 1024
        const int p    = grow & (P - 1);
        float x = 0.0f;
        if (lane < M)
            x = task[n * (M * P) + lane * P + p];   // lane = m index
        x += __shfl_xor_sync(0xFFFFFFFFu, x, 8);
        x += __shfl_xor_sync(0xFFFFFFFFu, x, 4);
        x += __shfl_xor_sync(0xFFFFFFFFu, x, 2);
        x += __shfl_xor_sync(0xFFFFFFFFu, x, 1);
        if (lane == 0)
            s_mean[w] = x * (1.0f / (float)M);
    }
    __syncthreads();

    // ---- 3) Multiply + store. Chunk k touches element e = k*512 + tid,
    //         local row = e>>7 = 4k + (w>>2)  (warp-uniform -> broadcast).
#pragma unroll
    for (int k = 0; k < U; ++k) {
        const float mn = s_mean[4 * k + (w >> 2)];
        v[k].x *= mn; v[k].y *= mn; v[k].z *= mn; v[k].w *= mn;
        o[base4 + k * TPB] = v[k];
    }
}

extern "C" void kernel_launch(void* const* d_in, const int* in_sizes, int n_in,
                              void* d_out, int out_size)
{
    const float* task = (const float*)d_in[0];   // [N, M, P]
    const float* feat = (const float*)d_in[1];   // [N, P, D]
    float* out = (float*)d_out;

    fused_kernel<<<GRID, TPB>>>(task, feat, out);
}